// round 2
// baseline (speedup 1.0000x reference)
#include <cuda_runtime.h>
#include <math.h>

#define BB 8
#define CC 64
#define HH 256
#define WW 256
#define MM 32
#define HWSZ 65536

// ---------------- scratch (device globals; no allocation) ----------------
__device__ float2 d_tab[HH * MM];     // [t][k] : cos/sin(2*pi*k*t/256)   64KB
__device__ float2 d_tabT[MM * HH];    // [k][t]                           64KB
__device__ float2 d_partial[64 * 32]; // BN partial (sum, sumsq)
__device__ float2 d_bn[64];           // (a, b): g = gelu(a*x + b)
__device__ float2 d_xft[BB * CC * MM * MM]; // 4MB  [b][c][ky][kx]
__device__ float2 d_om [BB * CC * MM * MM]; // 4MB  [b][o][ky][kx]
__device__ float2 d_Z  [BB * HH * CC * MM]; // 32MB [b][h][o][kx]

// ---------------- twiddle tables ----------------
__global__ void k_tab() {
    int t = blockIdx.x, k = threadIdx.x;
    int m = (k * t) & 255;                 // exact: k*t < 2^24
    float s, c;
    sincospif((float)m * (2.0f / 256.0f), &s, &c);
    d_tab [t * MM + k] = make_float2(c, s);
    d_tabT[k * HH + t] = make_float2(c, s);
}

// ---------------- BN stats: partial ----------------
__global__ __launch_bounds__(256) void k_bnp(const float* __restrict__ x) {
    int c = blockIdx.x, j = blockIdx.y;
    const float* p = x + ((size_t)(j >> 2) * 64 + c) * HWSZ + (size_t)(j & 3) * 16384;
    float s = 0.f, s2 = 0.f;
    #pragma unroll 8
    for (int i = 0; i < 64; i++) {
        float v = p[i * 256 + threadIdx.x];
        s += v; s2 += v * v;
    }
    #pragma unroll
    for (int o = 16; o; o >>= 1) {
        s  += __shfl_xor_sync(0xFFFFFFFFu, s,  o);
        s2 += __shfl_xor_sync(0xFFFFFFFFu, s2, o);
    }
    __shared__ float2 red[8];
    int w = threadIdx.x >> 5;
    if ((threadIdx.x & 31) == 0) red[w] = make_float2(s, s2);
    __syncthreads();
    if (threadIdx.x == 0) {
        float a = 0.f, b = 0.f;
        for (int i = 0; i < 8; i++) { a += red[i].x; b += red[i].y; }
        d_partial[c * 32 + j] = make_float2(a, b);
    }
}

// ---------------- BN stats: final ----------------
__global__ void k_bnf(const float* __restrict__ gamma, const float* __restrict__ beta) {
    int c = threadIdx.x;
    float s = 0.f, s2 = 0.f;
    for (int i = 0; i < 32; i++) { float2 p = d_partial[c * 32 + i]; s += p.x; s2 += p.y; }
    const float inv = 1.0f / 524288.0f;
    float mean = s * inv;
    float var  = s2 * inv - mean * mean;
    float istd = rsqrtf(var + 1e-5f);
    float a = gamma[c] * istd;
    d_bn[c] = make_float2(a, beta[c] - mean * a);
}

// ---------------- forward partial DFT (fused 2-stage), one block per (b,c) ----------------
// smem: tabs 64KB + Xw 64KB + x-tile 32KB = 160KB
extern __shared__ unsigned char smraw[];
__global__ __launch_bounds__(256) void k_fwd(const float* __restrict__ x) {
    float2* tabs = (float2*)smraw;            // [t][k] 8192 f2
    float2* xw   = tabs + HH * MM;            // [h][kx] 8192 f2
    float*  xs   = (float*)(xw + HH * MM);    // [32][256]
    int tid = threadIdx.x;
    // load tables (coalesced)
    {
        const float4* src = (const float4*)d_tab;
        float4* dst = (float4*)tabs;
        #pragma unroll
        for (int i = 0; i < 16; i++) dst[tid + 256 * i] = src[tid + 256 * i];
    }
    const float* xp = x + (size_t)blockIdx.x * HWSZ;
    int kx = tid & 31, hl = tid >> 5;

    // ---- stage 1: Xw[h][kx] = sum_w x[h][w] * e^{-2pi i kx w/256}
    for (int tile = 0; tile < 8; tile++) {
        __syncthreads();
        {
            const float4* src = (const float4*)(xp + tile * 8192);
            float4* dst = (float4*)xs;
            #pragma unroll
            for (int i = 0; i < 8; i++) dst[tid + 256 * i] = src[tid + 256 * i];
        }
        __syncthreads();
        float ar0=0,ai0=0,ar1=0,ai1=0,ar2=0,ai2=0,ar3=0,ai3=0;
        const float *r0 = xs + hl * 256, *r1 = xs + (hl + 8) * 256,
                    *r2 = xs + (hl + 16) * 256, *r3 = xs + (hl + 24) * 256;
        #pragma unroll 4
        for (int w = 0; w < 256; w++) {
            float2 cs = tabs[w * MM + kx];
            float x0 = r0[w], x1 = r1[w], x2 = r2[w], x3 = r3[w];
            ar0 = fmaf(x0,  cs.x, ar0); ai0 = fmaf(x0, -cs.y, ai0);
            ar1 = fmaf(x1,  cs.x, ar1); ai1 = fmaf(x1, -cs.y, ai1);
            ar2 = fmaf(x2,  cs.x, ar2); ai2 = fmaf(x2, -cs.y, ai2);
            ar3 = fmaf(x3,  cs.x, ar3); ai3 = fmaf(x3, -cs.y, ai3);
        }
        int hb = tile * 32;
        xw[(hb + hl     ) * MM + kx] = make_float2(ar0, ai0);
        xw[(hb + hl +  8) * MM + kx] = make_float2(ar1, ai1);
        xw[(hb + hl + 16) * MM + kx] = make_float2(ar2, ai2);
        xw[(hb + hl + 24) * MM + kx] = make_float2(ar3, ai3);
    }
    __syncthreads();

    // ---- stage 2: xft[ky][kx] = sum_h e^{-2pi i ky h/256} * Xw[h][kx]
    int kyg = hl; // 0..7 ; thread handles ky = kyg + 8r
    float2 o0 = {0,0}, o1 = {0,0}, o2 = {0,0}, o3 = {0,0};
    #pragma unroll 2
    for (int h = 0; h < 256; h++) {
        float2 X  = xw[h * MM + kx];
        float2 c0 = tabs[h * MM + kyg];
        float2 c1 = tabs[h * MM + kyg + 8];
        float2 c2 = tabs[h * MM + kyg + 16];
        float2 c3 = tabs[h * MM + kyg + 24];
        o0.x = fmaf(c0.x, X.x, fmaf( c0.y, X.y, o0.x));
        o0.y = fmaf(c0.x, X.y, fmaf(-c0.y, X.x, o0.y));
        o1.x = fmaf(c1.x, X.x, fmaf( c1.y, X.y, o1.x));
        o1.y = fmaf(c1.x, X.y, fmaf(-c1.y, X.x, o1.y));
        o2.x = fmaf(c2.x, X.x, fmaf( c2.y, X.y, o2.x));
        o2.y = fmaf(c2.x, X.y, fmaf(-c2.y, X.x, o2.y));
        o3.x = fmaf(c3.x, X.x, fmaf( c3.y, X.y, o3.x));
        o3.y = fmaf(c3.x, X.y, fmaf(-c3.y, X.x, o3.y));
    }
    float2* dst = d_xft + (size_t)blockIdx.x * 1024;
    dst[(kyg     ) * 32 + kx] = o0;
    dst[(kyg +  8) * 32 + kx] = o1;
    dst[(kyg + 16) * 32 + kx] = o2;
    dst[(kyg + 24) * 32 + kx] = o3;
}

// ---------------- channel mix: out_modes[b,o,m] = sum_c xft[b,c,m] * (wr+i*wi)[c,o,m] ----------------
// grid: (mode-tile 8, o-tile 8, b-tile 2), 128 threads; all loads coalesced over m
__global__ __launch_bounds__(128) void k_mix(const float* __restrict__ wr_g,
                                             const float* __restrict__ wi_g) {
    int m  = blockIdx.x * 128 + threadIdx.x;
    int o0 = blockIdx.y * 8;
    int b0 = blockIdx.z * 4;
    float accr[8][4], acci[8][4];
    #pragma unroll
    for (int j = 0; j < 8; j++)
        #pragma unroll
        for (int t = 0; t < 4; t++) { accr[j][t] = 0.f; acci[j][t] = 0.f; }
    for (int c = 0; c < 64; c++) {
        float wr[8], wi[8];
        #pragma unroll
        for (int j = 0; j < 8; j++) {
            int ofs = (c * 64 + o0 + j) * 1024 + m;
            wr[j] = wr_g[ofs]; wi[j] = wi_g[ofs];
        }
        float2 xv[4];
        #pragma unroll
        for (int t = 0; t < 4; t++) xv[t] = d_xft[((size_t)(b0 + t) * 64 + c) * 1024 + m];
        #pragma unroll
        for (int j = 0; j < 8; j++)
            #pragma unroll
            for (int t = 0; t < 4; t++) {
                accr[j][t] = fmaf(xv[t].x, wr[j], fmaf(-xv[t].y, wi[j], accr[j][t]));
                acci[j][t] = fmaf(xv[t].x, wi[j], fmaf( xv[t].y, wr[j], acci[j][t]));
            }
    }
    #pragma unroll
    for (int j = 0; j < 8; j++)
        #pragma unroll
        for (int t = 0; t < 4; t++)
            d_om[((size_t)(b0 + t) * 64 + o0 + j) * 1024 + m] = make_float2(accr[j][t], acci[j][t]);
}

// ---------------- inverse stage 1: Z[b,h,o,kx] = sum_ky OMs[ky,kx] e^{+2pi i ky h/256} ----------------
// scaling c_kx * fft_scale / (H*W) folded into OMs. smem: tabs 64KB + oms 8KB
__global__ __launch_bounds__(256) void k_inv1(const float* __restrict__ fscale) {
    float2* tabs = (float2*)smraw;
    float2* oms  = tabs + HH * MM;
    int o = blockIdx.x, b = blockIdx.y;
    int tid = threadIdx.x;
    {
        const float4* src = (const float4*)d_tab;
        float4* dst = (float4*)tabs;
        #pragma unroll
        for (int i = 0; i < 16; i++) dst[tid + 256 * i] = src[tid + 256 * i];
    }
    float fs = fscale[0] * (1.0f / 65536.0f);
    const float2* omg = d_om + ((size_t)b * 64 + o) * 1024;
    #pragma unroll
    for (int i = 0; i < 4; i++) {
        int idx = tid + 256 * i;
        int kxi = idx & 31;
        float sc = (kxi == 0 ? 1.0f : 2.0f) * fs;
        float2 v = omg[idx];
        oms[idx] = make_float2(v.x * sc, v.y * sc);
    }
    __syncthreads();
    int kx = tid & 31, hg = tid >> 5;
    float2* zout = d_Z + (size_t)b * 256 * 2048 + o * 32;
    for (int j = 0; j < 32; j++) {
        int h = hg + 8 * j;
        float zr = 0.f, zi = 0.f;
        #pragma unroll 8
        for (int ky = 0; ky < 32; ky++) {
            float2 cs = tabs[h * 32 + ky];
            float2 om = oms[ky * 32 + kx];
            zr = fmaf(cs.x, om.x, fmaf(-cs.y, om.y, zr));
            zi = fmaf(cs.x, om.y, fmaf( cs.y, om.x, zi));
        }
        zout[(size_t)h * 2048 + kx] = make_float2(zr, zi);
    }
}

// ---------------- final fused: inverse stage2 + BN + GELU + 1x1 conv + bias + skip ----------------
// block per (h, b); 256 threads = 256 w columns; each thread owns acc[64 o]
__global__ __launch_bounds__(256) void k_final(const float* __restrict__ x,
                                               const float* __restrict__ pw,
                                               const float* __restrict__ pb,
                                               float* __restrict__ out) {
    float*  xs   = (float*)smraw;        // [64 c][256 w]        64KB
    float*  pwT  = xs + 16384;           // [64 i][64 o]         16KB
    float*  zre  = pwT + 4096;           // [32 kx][64 o]         8KB
    float*  zim  = zre + 2048;           //                       8KB
    float*  bias = zim + 2048;           // [64]
    float2* bnv  = (float2*)(bias + 64); // [64]
    int h = blockIdx.x, b = blockIdx.y;
    int tid = threadIdx.x;

    const float* xb = x + (size_t)b * 64 * HWSZ;
    #pragma unroll
    for (int i = 0; i < 16; i++) {
        int idx = tid + 256 * i;          // float4 index 0..4095
        int c = idx >> 6, w4 = idx & 63;
        ((float4*)xs)[idx] = *(const float4*)(xb + (size_t)c * HWSZ + h * 256 + w4 * 4);
    }
    #pragma unroll
    for (int i = 0; i < 16; i++) {
        int idx = tid + 256 * i;          // 0..4095
        int o = idx >> 6, ii = idx & 63;
        pwT[ii * 64 + o] = pw[idx];
    }
    {
        const float2* zg = d_Z + ((size_t)b * 256 + h) * 2048;
        #pragma unroll
        for (int i = 0; i < 8; i++) {
            int idx = tid + 256 * i;      // 0..2047 ; [o][kx]
            int o = idx >> 5, kxi = idx & 31;
            float2 v = zg[idx];
            zre[kxi * 64 + o] = v.x;
            zim[kxi * 64 + o] = v.y;
        }
    }
    if (tid < 64) { bias[tid] = pb[tid]; bnv[tid] = d_bn[tid]; }
    __syncthreads();

    int w = tid;
    float acc[64];
    #pragma unroll
    for (int o = 0; o < 64; o++) acc[o] = 0.f;

    // projection branch: BN -> GELU(exact) -> 1x1 conv
    for (int i = 0; i < 64; i++) {
        float2 ab = bnv[i];
        float xn = fmaf(xs[i * 256 + w], ab.x, ab.y);
        float g  = 0.5f * xn * (1.0f + erff(xn * 0.70710678118654752f));
        #pragma unroll
        for (int o4 = 0; o4 < 16; o4++) {
            float4 p4 = *(const float4*)&pwT[i * 64 + o4 * 4];
            acc[o4*4+0] = fmaf(p4.x, g, acc[o4*4+0]);
            acc[o4*4+1] = fmaf(p4.y, g, acc[o4*4+1]);
            acc[o4*4+2] = fmaf(p4.z, g, acc[o4*4+2]);
            acc[o4*4+3] = fmaf(p4.w, g, acc[o4*4+3]);
        }
    }
    // spectral branch, stage 2: xf += zre*cos - zim*sin (scales pre-folded)
    for (int kx = 0; kx < 32; kx++) {
        float2 cs = __ldg(&d_tabT[kx * 256 + w]);
        #pragma unroll
        for (int o4 = 0; o4 < 16; o4++) {
            float4 zr = *(const float4*)&zre[kx * 64 + o4 * 4];
            float4 zi = *(const float4*)&zim[kx * 64 + o4 * 4];
            acc[o4*4+0] = fmaf(zr.x, cs.x, fmaf(zi.x, -cs.y, acc[o4*4+0]));
            acc[o4*4+1] = fmaf(zr.y, cs.x, fmaf(zi.y, -cs.y, acc[o4*4+1]));
            acc[o4*4+2] = fmaf(zr.z, cs.x, fmaf(zi.z, -cs.y, acc[o4*4+2]));
            acc[o4*4+3] = fmaf(zr.w, cs.x, fmaf(zi.w, -cs.y, acc[o4*4+3]));
        }
    }
    // bias + identity skip + store
    float* ob = out + (size_t)b * 64 * HWSZ + h * 256 + w;
    #pragma unroll
    for (int o = 0; o < 64; o++)
        ob[(size_t)o * HWSZ] = acc[o] + bias[o] + xs[o * 256 + w];
}

// ---------------- launch ----------------
extern "C" void kernel_launch(void* const* d_in, const int* in_sizes, int n_in,
                              void* d_out, int out_size) {
    const float* x     = (const float*)d_in[0];
    const float* wr    = (const float*)d_in[1];
    const float* wi    = (const float*)d_in[2];
    const float* fs    = (const float*)d_in[3];
    const float* gamma = (const float*)d_in[4];
    const float* beta  = (const float*)d_in[5];
    const float* pw    = (const float*)d_in[6];
    const float* pb    = (const float*)d_in[7];
    float* out = (float*)d_out;

    cudaFuncSetAttribute(k_fwd,   cudaFuncAttributeMaxDynamicSharedMemorySize, 163840);
    cudaFuncSetAttribute(k_inv1,  cudaFuncAttributeMaxDynamicSharedMemorySize, 73728);
    cudaFuncSetAttribute(k_final, cudaFuncAttributeMaxDynamicSharedMemorySize, 99072);

    k_tab<<<256, 32>>>();
    k_bnp<<<dim3(64, 32), 256>>>(x);
    k_bnf<<<1, 64>>>(gamma, beta);
    k_fwd<<<512, 256, 163840>>>(x);
    k_mix<<<dim3(8, 8, 2), 128>>>(wr, wi);
    k_inv1<<<dim3(64, 8), 256, 73728>>>(fs);
    k_final<<<dim3(256, 8), 256, 99072>>>(x, pw, pb, out);
}

// round 3
// speedup vs baseline: 1.2960x; 1.2960x over previous
#include <cuda_runtime.h>
#include <math.h>

#define HWSZ 65536

// ---------------- scratch (device globals; no allocation) ----------------
__device__ float2 d_tab [256 * 32];   // [t][k] : (cos, sin)(2*pi*k*t/256)
__device__ float2 d_tabT[32 * 256];   // [k][t]
__device__ float4 d_tabP[128 * 16];   // [w<128][kxp] : (c0, c1, -s0, -s1) for kx pair
__device__ float2 d_partial[64 * 32];
__device__ float2 d_bn[64];
__device__ float2 d_Xw [512 * 256 * 32];   // 33.5MB [b*64+c][h][kx]
__device__ float2 d_xft[8 * 64 * 32 * 32]; // 4MB  [b][c][ky][kx]
__device__ float2 d_om [8 * 64 * 32 * 32]; // 4MB  [b][o][ky][kx]
__device__ float2 d_Z  [8 * 256 * 64 * 32];// 32MB [b][h][o][kx]

// packed f32x2 FMA: d += a * b (component-wise)
__device__ __forceinline__ void fma2p(float2& d, float2 a, float2 b) {
    asm("fma.rn.f32x2 %0, %1, %2, %0;"
        : "+l"(reinterpret_cast<unsigned long long&>(d))
        : "l"(reinterpret_cast<const unsigned long long&>(a)),
          "l"(reinterpret_cast<const unsigned long long&>(b)));
}

// ---------------- twiddle tables ----------------
__global__ void k_tab() {
    __shared__ float2 row[32];
    int t = blockIdx.x, k = threadIdx.x;
    int m = (k * t) & 255;
    float s, c;
    sincospif((float)m * (1.0f / 128.0f), &s, &c);
    d_tab [t * 32 + k]  = make_float2(c, s);
    d_tabT[k * 256 + t] = make_float2(c, s);
    row[k] = make_float2(c, s);
    __syncwarp();
    if (t < 128 && k < 16) {
        float2 a = row[2 * k], b = row[2 * k + 1];
        d_tabP[t * 16 + k] = make_float4(a.x, b.x, -a.y, -b.y);
    }
}

// ---------------- BN stats: partial ----------------
__global__ __launch_bounds__(256) void k_bnp(const float* __restrict__ x) {
    int c = blockIdx.x, j = blockIdx.y;
    const float* p = x + ((size_t)(j >> 2) * 64 + c) * HWSZ + (size_t)(j & 3) * 16384;
    float s = 0.f, s2 = 0.f;
    #pragma unroll 8
    for (int i = 0; i < 64; i++) {
        float v = p[i * 256 + threadIdx.x];
        s += v; s2 += v * v;
    }
    #pragma unroll
    for (int o = 16; o; o >>= 1) {
        s  += __shfl_xor_sync(0xFFFFFFFFu, s,  o);
        s2 += __shfl_xor_sync(0xFFFFFFFFu, s2, o);
    }
    __shared__ float2 red[8];
    int w = threadIdx.x >> 5;
    if ((threadIdx.x & 31) == 0) red[w] = make_float2(s, s2);
    __syncthreads();
    if (threadIdx.x == 0) {
        float a = 0.f, b = 0.f;
        for (int i = 0; i < 8; i++) { a += red[i].x; b += red[i].y; }
        d_partial[c * 32 + j] = make_float2(a, b);
    }
}

// ---------------- BN stats: final ----------------
__global__ void k_bnf(const float* __restrict__ gamma, const float* __restrict__ beta) {
    int c = threadIdx.x;
    float s = 0.f, s2 = 0.f;
    for (int i = 0; i < 32; i++) { float2 p = d_partial[c * 32 + i]; s += p.x; s2 += p.y; }
    const float inv = 1.0f / 524288.0f;
    float mean = s * inv;
    float var  = s2 * inv - mean * mean;
    float istd = rsqrtf(var + 1e-5f);
    float a = gamma[c] * istd;
    d_bn[c] = make_float2(a, beta[c] - mean * a);
}

extern __shared__ unsigned char smraw[];

// ---------------- forward stage 1: Xw[h][kx] = sum_w x[h][w] e^{-2pi i kx w/256} ----------------
// w-halving: Xw[kx] = sum_{w<128} T(w,kx) * (kx even ? x(w)+x(w+128) : x(w)-x(w+128))
// thread = (hl 0..15, kxp 0..15); 2 rows, 2 kx (packed f32x2). smem 64KB -> 3 CTAs/SM
__global__ __launch_bounds__(256) void k_s1(const float* __restrict__ x) {
    float4* tabP = (float4*)smraw;           // 2048 f4 = 32KB
    float2* eo   = (float2*)(tabP + 2048);   // 32 rows * 128 = 32KB
    int tid = threadIdx.x;
    #pragma unroll
    for (int i = 0; i < 8; i++) tabP[tid + 256 * i] = d_tabP[tid + 256 * i];
    const float* xp = x + (size_t)blockIdx.x * HWSZ;
    int kxp = tid & 15, hl = tid >> 4;
    float4* xw4 = (float4*)(d_Xw + (size_t)blockIdx.x * 8192);

    for (int tile = 0; tile < 8; tile++) {
        __syncthreads();
        #pragma unroll
        for (int i = 0; i < 16; i++) {
            int idx = tid + 256 * i;          // 0..4095
            int row = idx >> 7, w = idx & 127;
            const float* rp = xp + (tile * 32 + row) * 256 + w;
            float a = rp[0], b = rp[128];
            eo[row * 128 + w] = make_float2(a + b, a - b);
        }
        __syncthreads();
        float2 ar0 = {0,0}, ai0 = {0,0}, ar1 = {0,0}, ai1 = {0,0};
        const float2* p0r = eo + hl * 128;
        const float2* p1r = eo + (hl + 16) * 128;
        #pragma unroll 4
        for (int w = 0; w < 128; w++) {
            float4 t4 = tabP[w * 16 + kxp];
            float2 CC = make_float2(t4.x, t4.y), SS = make_float2(t4.z, t4.w);
            float2 p0 = p0r[w], p1 = p1r[w];
            fma2p(ar0, CC, p0); fma2p(ai0, SS, p0);
            fma2p(ar1, CC, p1); fma2p(ai1, SS, p1);
        }
        int r0 = tile * 32 + hl;
        xw4[r0 * 16 + kxp]        = make_float4(ar0.x, ai0.x, ar0.y, ai0.y);
        xw4[(r0 + 16) * 16 + kxp] = make_float4(ar1.x, ai1.x, ar1.y, ai1.y);
    }
}

// ---------------- forward stage 2: xft[ky][kx] = sum_h e^{-2pi i ky h/256} Xw[h][kx] ----------------
// h-halving: use P = Xw(h) + (-1)^ky Xw(h+128); ky parity constant per thread. smem 32KB
__global__ __launch_bounds__(256) void k_s2() {
    float2* tabs = (float2*)smraw;           // rows h<128: 4096 f2 = 32KB
    int tid = threadIdx.x;
    {
        const float4* src = (const float4*)d_tab;
        float4* dst = (float4*)tabs;
        #pragma unroll
        for (int i = 0; i < 8; i++) dst[tid + 256 * i] = src[tid + 256 * i];
    }
    __syncthreads();
    int kx = tid & 31, kyg = tid >> 5;
    float sgn = (kyg & 1) ? -1.f : 1.f;
    const float2* Xp = d_Xw + (size_t)blockIdx.x * 8192;
    float2 o0 = {0,0}, o1 = {0,0}, o2 = {0,0}, o3 = {0,0};
    #pragma unroll 2
    for (int h = 0; h < 128; h++) {
        float2 Xa = Xp[h * 32 + kx], Xb = Xp[(h + 128) * 32 + kx];
        float2 P;
        P.x = fmaf(sgn, Xb.x, Xa.x);
        P.y = fmaf(sgn, Xb.y, Xa.y);
        float2 c0 = tabs[h * 32 + kyg],      c1 = tabs[h * 32 + kyg + 8],
               c2 = tabs[h * 32 + kyg + 16], c3 = tabs[h * 32 + kyg + 24];
        o0.x = fmaf(c0.x, P.x, fmaf( c0.y, P.y, o0.x));
        o0.y = fmaf(c0.x, P.y, fmaf(-c0.y, P.x, o0.y));
        o1.x = fmaf(c1.x, P.x, fmaf( c1.y, P.y, o1.x));
        o1.y = fmaf(c1.x, P.y, fmaf(-c1.y, P.x, o1.y));
        o2.x = fmaf(c2.x, P.x, fmaf( c2.y, P.y, o2.x));
        o2.y = fmaf(c2.x, P.y, fmaf(-c2.y, P.x, o2.y));
        o3.x = fmaf(c3.x, P.x, fmaf( c3.y, P.y, o3.x));
        o3.y = fmaf(c3.x, P.y, fmaf(-c3.y, P.x, o3.y));
    }
    float2* dst = d_xft + (size_t)blockIdx.x * 1024;
    dst[kyg * 32 + kx]        = o0;
    dst[(kyg +  8) * 32 + kx] = o1;
    dst[(kyg + 16) * 32 + kx] = o2;
    dst[(kyg + 24) * 32 + kx] = o3;
}

// ---------------- channel mix (unchanged) ----------------
__global__ __launch_bounds__(128) void k_mix(const float* __restrict__ wr_g,
                                             const float* __restrict__ wi_g) {
    int m  = blockIdx.x * 128 + threadIdx.x;
    int o0 = blockIdx.y * 8;
    int b0 = blockIdx.z * 4;
    float accr[8][4], acci[8][4];
    #pragma unroll
    for (int j = 0; j < 8; j++)
        #pragma unroll
        for (int t = 0; t < 4; t++) { accr[j][t] = 0.f; acci[j][t] = 0.f; }
    for (int c = 0; c < 64; c++) {
        float wr[8], wi[8];
        #pragma unroll
        for (int j = 0; j < 8; j++) {
            int ofs = (c * 64 + o0 + j) * 1024 + m;
            wr[j] = wr_g[ofs]; wi[j] = wi_g[ofs];
        }
        float2 xv[4];
        #pragma unroll
        for (int t = 0; t < 4; t++) xv[t] = d_xft[((size_t)(b0 + t) * 64 + c) * 1024 + m];
        #pragma unroll
        for (int j = 0; j < 8; j++)
            #pragma unroll
            for (int t = 0; t < 4; t++) {
                accr[j][t] = fmaf(xv[t].x, wr[j], fmaf(-xv[t].y, wi[j], accr[j][t]));
                acci[j][t] = fmaf(xv[t].x, wi[j], fmaf( xv[t].y, wr[j], acci[j][t]));
            }
    }
    #pragma unroll
    for (int j = 0; j < 8; j++)
        #pragma unroll
        for (int t = 0; t < 4; t++)
            d_om[((size_t)(b0 + t) * 64 + o0 + j) * 1024 + m] = make_float2(accr[j][t], acci[j][t]);
}

// ---------------- inverse stage 1 with h-halving: Z(h), Z(h+128) from even/odd-ky sums ----------------
// smem: half tab 32KB + oms 8KB = 40KB
__global__ __launch_bounds__(256) void k_inv1(const float* __restrict__ fscale) {
    float2* tabs = (float2*)smraw;          // h<128 rows
    float2* oms  = tabs + 4096;             // 1024 f2
    int o = blockIdx.x, b = blockIdx.y, tid = threadIdx.x;
    {
        const float4* src = (const float4*)d_tab;
        float4* dst = (float4*)tabs;
        #pragma unroll
        for (int i = 0; i < 8; i++) dst[tid + 256 * i] = src[tid + 256 * i];
    }
    float fs = fscale[0] * (1.0f / 65536.0f);
    const float2* omg = d_om + ((size_t)b * 64 + o) * 1024;
    #pragma unroll
    for (int i = 0; i < 4; i++) {
        int idx = tid + 256 * i;
        int kxi = idx & 31;
        float sc = (kxi == 0 ? 1.0f : 2.0f) * fs;
        float2 v = omg[idx];
        oms[idx] = make_float2(v.x * sc, v.y * sc);
    }
    __syncthreads();
    int kx = tid & 31, hg = tid >> 5;
    float2* zout = d_Z + (size_t)b * 256 * 2048 + o * 32;
    for (int jp = 0; jp < 16; jp++) {
        int h = hg + 8 * jp;                // 0..127
        float SEr = 0, SEi = 0, SOr = 0, SOi = 0;
        #pragma unroll 4
        for (int kyp = 0; kyp < 16; kyp++) {
            float2 ce = tabs[h * 32 + 2 * kyp], co = tabs[h * 32 + 2 * kyp + 1];
            float2 oe = oms[(2 * kyp) * 32 + kx], oo = oms[(2 * kyp + 1) * 32 + kx];
            SEr = fmaf(ce.x, oe.x, fmaf(-ce.y, oe.y, SEr));
            SEi = fmaf(ce.x, oe.y, fmaf( ce.y, oe.x, SEi));
            SOr = fmaf(co.x, oo.x, fmaf(-co.y, oo.y, SOr));
            SOi = fmaf(co.x, oo.y, fmaf( co.y, oo.x, SOi));
        }
        zout[(size_t)h * 2048 + kx]         = make_float2(SEr + SOr, SEi + SOi);
        zout[(size_t)(h + 128) * 2048 + kx] = make_float2(SEr - SOr, SEi - SOi);
    }
}

// ---------------- final fused: inv stage2 + BN + GELU + 1x1 conv + bias + skip (f32x2 packed) ----------------
__global__ __launch_bounds__(256, 2) void k_final(const float* __restrict__ x,
                                                  const float* __restrict__ pw,
                                                  const float* __restrict__ pb,
                                                  float* __restrict__ out) {
    float*  xs   = (float*)smraw;        // [64 c][256 w]  64KB
    float*  pwT  = xs + 16384;           // [64 i][64 o]   16KB
    float*  zre  = pwT + 4096;           // [32 kx][64 o]   8KB
    float*  zim  = zre + 2048;           //                 8KB
    float*  bias = zim + 2048;           // [64]
    float2* bnv  = (float2*)(bias + 64); // [64]
    int h = blockIdx.x, b = blockIdx.y;
    int tid = threadIdx.x;

    const float* xb = x + (size_t)b * 64 * HWSZ;
    #pragma unroll
    for (int i = 0; i < 16; i++) {
        int idx = tid + 256 * i;
        int c = idx >> 6, w4 = idx & 63;
        ((float4*)xs)[idx] = *(const float4*)(xb + (size_t)c * HWSZ + h * 256 + w4 * 4);
    }
    #pragma unroll
    for (int i = 0; i < 16; i++) {
        int idx = tid + 256 * i;
        int o = idx >> 6, ii = idx & 63;
        pwT[ii * 64 + o] = pw[idx];
    }
    {
        const float2* zg = d_Z + ((size_t)b * 256 + h) * 2048;
        #pragma unroll
        for (int i = 0; i < 8; i++) {
            int idx = tid + 256 * i;      // [o][kx]
            int o = idx >> 5, kxi = idx & 31;
            float2 v = zg[idx];
            zre[kxi * 64 + o] = v.x;
            zim[kxi * 64 + o] = v.y;
        }
    }
    if (tid < 64) { bias[tid] = pb[tid]; bnv[tid] = d_bn[tid]; }
    __syncthreads();

    int w = tid;
    float2 acc[32];
    #pragma unroll
    for (int j = 0; j < 32; j++) acc[j] = make_float2(0.f, 0.f);

    // projection branch: BN -> GELU(exact) -> 1x1 conv, packed over o pairs
    const float4* pwT4 = (const float4*)pwT;
    for (int i = 0; i < 64; i++) {
        float2 ab = bnv[i];
        float xn = fmaf(xs[i * 256 + w], ab.x, ab.y);
        float g  = 0.5f * xn * (1.0f + erff(xn * 0.70710678118654752f));
        float2 gg = make_float2(g, g);
        #pragma unroll
        for (int j = 0; j < 16; j++) {
            float4 p4 = pwT4[i * 16 + j];
            fma2p(acc[2 * j],     gg, make_float2(p4.x, p4.y));
            fma2p(acc[2 * j + 1], gg, make_float2(p4.z, p4.w));
        }
    }
    // spectral stage 2: acc += zre*cos - zim*sin, packed over o pairs
    const float4* zre4 = (const float4*)zre;
    const float4* zim4 = (const float4*)zim;
    for (int kx = 0; kx < 32; kx++) {
        float2 cs = __ldg(&d_tabT[kx * 256 + w]);
        float2 CC = make_float2(cs.x, cs.x);
        float2 SN = make_float2(-cs.y, -cs.y);
        #pragma unroll
        for (int j = 0; j < 16; j++) {
            float4 zr = zre4[kx * 16 + j];
            float4 zi = zim4[kx * 16 + j];
            fma2p(acc[2 * j],     CC, make_float2(zr.x, zr.y));
            fma2p(acc[2 * j],     SN, make_float2(zi.x, zi.y));
            fma2p(acc[2 * j + 1], CC, make_float2(zr.z, zr.w));
            fma2p(acc[2 * j + 1], SN, make_float2(zi.z, zi.w));
        }
    }
    // bias + identity skip + store
    float* ob = out + (size_t)b * 64 * HWSZ + h * 256 + w;
    #pragma unroll
    for (int j = 0; j < 32; j++) {
        int o0 = 2 * j, o1 = 2 * j + 1;
        ob[(size_t)o0 * HWSZ] = acc[j].x + bias[o0] + xs[o0 * 256 + w];
        ob[(size_t)o1 * HWSZ] = acc[j].y + bias[o1] + xs[o1 * 256 + w];
    }
}

// ---------------- launch ----------------
extern "C" void kernel_launch(void* const* d_in, const int* in_sizes, int n_in,
                              void* d_out, int out_size) {
    const float* x     = (const float*)d_in[0];
    const float* wr    = (const float*)d_in[1];
    const float* wi    = (const float*)d_in[2];
    const float* fs    = (const float*)d_in[3];
    const float* gamma = (const float*)d_in[4];
    const float* beta  = (const float*)d_in[5];
    const float* pw    = (const float*)d_in[6];
    const float* pb    = (const float*)d_in[7];
    float* out = (float*)d_out;

    cudaFuncSetAttribute(k_s1,    cudaFuncAttributeMaxDynamicSharedMemorySize, 65536);
    cudaFuncSetAttribute(k_s2,    cudaFuncAttributeMaxDynamicSharedMemorySize, 32768);
    cudaFuncSetAttribute(k_inv1,  cudaFuncAttributeMaxDynamicSharedMemorySize, 40960);
    cudaFuncSetAttribute(k_final, cudaFuncAttributeMaxDynamicSharedMemorySize, 99072);

    k_tab<<<256, 32>>>();
    k_bnp<<<dim3(64, 32), 256>>>(x);
    k_bnf<<<1, 64>>>(gamma, beta);
    k_s1<<<512, 256, 65536>>>(x);
    k_s2<<<512, 256, 32768>>>();
    k_mix<<<dim3(8, 8, 2), 128>>>(wr, wi);
    k_inv1<<<dim3(64, 8), 256, 40960>>>(fs);
    k_final<<<dim3(256, 8), 256, 99072>>>(x, pw, pb, out);
}